// round 5
// baseline (speedup 1.0000x reference)
#include <cuda_runtime.h>
#include <cuda_bf16.h>
#include <math.h>

#define NN 100000
#define EE 1600000
#define DD 64
#define CC 2

// Static device scratch (no allocation allowed)
__device__ int2   g_rc[EE];    // packed (row, col) per edge
__device__ int    g_deg[NN];   // in-degree WITHOUT self loop (starts at 0)
__device__ float  g_dinv[NN];
__device__ float2 g_z0[NN];    // dinv * (x @ W.T)
__device__ float4 g_a1[NN];    // .xy = hop-1 accumulator t1, .z = dinv^2
__device__ float2 g_t2[NN];    // hop-2 accumulator
__device__ int    g_is64;

// no-return reductions (REDG)
__device__ __forceinline__ void red_add_f2(float2* p, float a, float b) {
    asm volatile("red.global.add.v2.f32 [%0], {%1, %2};"
                 :: "l"(p), "f"(a), "f"(b) : "memory");
}
__device__ __forceinline__ void red_add_1(int* p) {
    asm volatile("red.global.add.s32 [%0], %1;" :: "l"(p), "r"(1) : "memory");
}

// ---------------- kernels ----------------

// dtype-width detect only (zeroing is done by graph memset nodes)
__global__ void k_detect(const void* __restrict__ edge, int n) {
    if (threadIdx.x != 0) return;
    const long long* e64 = (const long long*)edge;
    int ok = 1;
    #pragma unroll 1
    for (int k = 0; k < 64; k++) {
        long long v = e64[k];
        if (v < 0 || v >= (long long)n) { ok = 0; break; }
    }
    g_is64 = ok;
}

// convert edge_index -> packed int2, count in-degree. 4 edges per thread.
__global__ void k_count(const void* __restrict__ edge, int e, int n) {
    int base = (blockIdx.x * blockDim.x + threadIdx.x) * 4;
    if (base >= e) return;
    int is64 = g_is64;
    int r[4], c[4];
    int m = min(4, e - base);
    if (is64) {
        const long long* e64 = (const long long*)edge;
        if (m == 4) {
            longlong2 r01 = *(const longlong2*)(e64 + base);
            longlong2 r23 = *(const longlong2*)(e64 + base + 2);
            longlong2 c01 = *(const longlong2*)(e64 + e + base);
            longlong2 c23 = *(const longlong2*)(e64 + e + base + 2);
            r[0] = (int)r01.x; r[1] = (int)r01.y; r[2] = (int)r23.x; r[3] = (int)r23.y;
            c[0] = (int)c01.x; c[1] = (int)c01.y; c[2] = (int)c23.x; c[3] = (int)c23.y;
        } else {
            for (int k = 0; k < m; k++) { r[k] = (int)e64[base + k]; c[k] = (int)e64[e + base + k]; }
        }
    } else {
        const int* e32 = (const int*)edge;
        if (m == 4) {
            int4 rr = *(const int4*)(e32 + base);
            int4 cc = *(const int4*)(e32 + e + base);
            r[0] = rr.x; r[1] = rr.y; r[2] = rr.z; r[3] = rr.w;
            c[0] = cc.x; c[1] = cc.y; c[2] = cc.z; c[3] = cc.w;
        } else {
            for (int k = 0; k < m; k++) { r[k] = e32[base + k]; c[k] = e32[e + base + k]; }
        }
    }
    #pragma unroll
    for (int k = 0; k < 4; k++) {
        if (k >= m) break;
        int rr = r[k], cc = c[k];
        if ((unsigned)rr >= (unsigned)n || (unsigned)cc >= (unsigned)n) { rr = 0; cc = 0; }
        g_rc[base + k] = make_int2(rr, cc);
        red_add_1(&g_deg[cc]);
    }
}

// warp-per-node: dinv (deg+1 for self loop) + scaled projection z0 = dinv*(x@W.T)
__global__ void k_proj(const float* __restrict__ x, const float* __restrict__ W, int n) {
    __shared__ float sW[2 * DD];
    int t = threadIdx.x;
    if (t < 2 * DD) sW[t] = W[t];
    __syncthreads();
    int gw = (blockIdx.x * blockDim.x + t) >> 5;
    int lane = t & 31;
    if (gw >= n) return;
    const float* xr = x + (size_t)gw * DD;
    float a  = xr[lane];
    float b2 = xr[lane + 32];
    float s0 = a * sW[lane]      + b2 * sW[lane + 32];
    float s1 = a * sW[DD + lane] + b2 * sW[DD + lane + 32];
    #pragma unroll
    for (int o = 16; o; o >>= 1) {
        s0 += __shfl_xor_sync(0xffffffffu, s0, o);
        s1 += __shfl_xor_sync(0xffffffffu, s1, o);
    }
    if (lane == 0) {
        float d = rsqrtf((float)(g_deg[gw] + 1));
        g_dinv[gw] = d;
        g_z0[gw] = make_float2(d * s0, d * s1);
        g_a1[gw].z = d * d;
    }
}

// hop 1: a1.xy[c] += z0[r]; edges [0,e) + self-loop tail [e, e+n)
__global__ void k_edge1(int e, int n) {
    int i = blockIdx.x * blockDim.x + threadIdx.x;
    if (i < e) {
        int2 rc = g_rc[i];
        float2 v = __ldg(&g_z0[rc.x]);
        red_add_f2((float2*)&g_a1[rc.y], v.x, v.y);
    } else if (i < e + n) {
        int j = i - e;
        float2 v = __ldg(&g_z0[j]);
        red_add_f2((float2*)&g_a1[j], v.x, v.y);
    }
}

// hop 2: t2[c] += d2[r]*t1[r], using the 16B a1 record (one sector per gather)
__global__ void k_edge2(int e, int n) {
    int i = blockIdx.x * blockDim.x + threadIdx.x;
    if (i < e) {
        int2 rc = g_rc[i];
        float4 a = __ldg(&g_a1[rc.x]);
        red_add_f2(&g_t2[rc.y], a.z * a.x, a.z * a.y);
    } else if (i < e + n) {
        int j = i - e;
        float4 a = __ldg(&g_a1[j]);
        red_add_f2(&g_t2[j], a.z * a.x, a.z * a.y);
    }
}

// out = log_softmax(dinv * t2 + b) over C=2
__global__ void k_out(const float* __restrict__ b, float* __restrict__ out, int n) {
    int i = blockIdx.x * blockDim.x + threadIdx.x;
    if (i >= n) return;
    float d = g_dinv[i];
    float2 y = g_t2[i];
    float l0 = d * y.x + b[0];
    float l1 = d * y.y + b[1];
    float m = fmaxf(l0, l1);
    float lse = m + logf(expf(l0 - m) + expf(l1 - m));
    *(float2*)(out + 2 * i) = make_float2(l0 - lse, l1 - lse);
}

// ---------------- launch ----------------

extern "C" void kernel_launch(void* const* d_in, const int* in_sizes, int n_in,
                              void* d_out, int out_size) {
    const float* x    = (const float*)d_in[0];
    const void*  edge = d_in[1];
    const float* W    = (const float*)d_in[2];
    const float* b    = (const float*)d_in[3];
    float*       out  = (float*)d_out;

    int n = in_sizes[0] / DD;   // 100000
    int e = in_sizes[1] / 2;    // 1600000

    void *p_deg, *p_a1, *p_t2;
    cudaGetSymbolAddress(&p_deg, g_deg);
    cudaGetSymbolAddress(&p_a1,  g_a1);
    cudaGetSymbolAddress(&p_t2,  g_t2);

    const int T = 256;
    int gn  = (n + T - 1) / T;
    int gc  = ((e + 3) / 4 + T - 1) / T;
    int gen = (e + n + T - 1) / T;
    int gw  = ((size_t)n * 32 + T - 1) / T;

    k_detect<<<1, 32>>>(edge, n);
    cudaMemsetAsync(p_deg, 0, (size_t)n * sizeof(int), 0);
    cudaMemsetAsync(p_a1,  0, (size_t)n * sizeof(float4), 0);
    cudaMemsetAsync(p_t2,  0, (size_t)n * sizeof(float2), 0);
    k_count<<<gc, T>>>(edge, e, n);
    k_proj<<<gw, T>>>(x, W, n);
    k_edge1<<<gen, T>>>(e, n);
    k_edge2<<<gen, T>>>(e, n);
    k_out<<<gn, T>>>(b, out, n);
}

// round 6
// speedup vs baseline: 1.0420x; 1.0420x over previous
#include <cuda_runtime.h>
#include <cuda_bf16.h>
#include <math.h>

#define NN 100000
#define EE 1600000
#define DD 64
#define CC 2

// Static device scratch (no allocation allowed)
__device__ int2   g_rc[EE];    // packed (row, col) per edge
__device__ int    g_deg[NN];   // in-degree WITH self loop (init 1)
__device__ float  g_dinv[NN];
__device__ float2 g_z0[NN];    // dinv * (x @ W.T)
__device__ float4 g_a1[NN];    // .xy = hop-1 accumulator t1, .z = dinv^2
__device__ float2 g_t2[NN];    // hop-2 accumulator
__device__ int    g_is64;

// no-return reductions (REDG)
__device__ __forceinline__ void red_add_f2(float2* p, float a, float b) {
    asm volatile("red.global.add.v2.f32 [%0], {%1, %2};"
                 :: "l"(p), "f"(a), "f"(b) : "memory");
}
__device__ __forceinline__ void red_add_1(int* p) {
    asm volatile("red.global.add.s32 [%0], %1;" :: "l"(p), "r"(1) : "memory");
}

// ---------------- kernels ----------------

// deg=1, a1=0, t2=0; thread (0,0) also detects edge dtype width.
__global__ void k_init(const void* __restrict__ edge, int n) {
    int i = blockIdx.x * blockDim.x + threadIdx.x;
    if (i == 0) {
        const long long* e64 = (const long long*)edge;
        int ok = 1;
        #pragma unroll 1
        for (int k = 0; k < 64; k++) {
            long long v = e64[k];
            if (v < 0 || v >= (long long)n) { ok = 0; break; }
        }
        g_is64 = ok;
    }
    if (i < n) {
        g_deg[i] = 1;
        g_a1[i] = make_float4(0.f, 0.f, 0.f, 0.f);
        g_t2[i] = make_float2(0.f, 0.f);
    }
}

// convert edge_index -> packed int2, count in-degree. 4 edges per thread.
__global__ void k_count(const void* __restrict__ edge, int e, int n) {
    int base = (blockIdx.x * blockDim.x + threadIdx.x) * 4;
    if (base >= e) return;
    int is64 = g_is64;
    int r[4], c[4];
    int m = min(4, e - base);
    if (is64) {
        const long long* e64 = (const long long*)edge;
        if (m == 4) {
            longlong2 r01 = *(const longlong2*)(e64 + base);
            longlong2 r23 = *(const longlong2*)(e64 + base + 2);
            longlong2 c01 = *(const longlong2*)(e64 + e + base);
            longlong2 c23 = *(const longlong2*)(e64 + e + base + 2);
            r[0] = (int)r01.x; r[1] = (int)r01.y; r[2] = (int)r23.x; r[3] = (int)r23.y;
            c[0] = (int)c01.x; c[1] = (int)c01.y; c[2] = (int)c23.x; c[3] = (int)c23.y;
        } else {
            for (int k = 0; k < m; k++) { r[k] = (int)e64[base + k]; c[k] = (int)e64[e + base + k]; }
        }
    } else {
        const int* e32 = (const int*)edge;
        if (m == 4) {
            int4 rr = *(const int4*)(e32 + base);
            int4 cc = *(const int4*)(e32 + e + base);
            r[0] = rr.x; r[1] = rr.y; r[2] = rr.z; r[3] = rr.w;
            c[0] = cc.x; c[1] = cc.y; c[2] = cc.z; c[3] = cc.w;
        } else {
            for (int k = 0; k < m; k++) { r[k] = e32[base + k]; c[k] = e32[e + base + k]; }
        }
    }
    #pragma unroll
    for (int k = 0; k < 4; k++) {
        if (k >= m) break;
        int rr = r[k], cc = c[k];
        if ((unsigned)rr >= (unsigned)n || (unsigned)cc >= (unsigned)n) { rr = 0; cc = 0; }
        g_rc[base + k] = make_int2(rr, cc);
        red_add_1(&g_deg[cc]);
    }
}

// warp-per-node: dinv + scaled projection z0 = dinv*(x@W.T); also a1.z = dinv^2
__global__ void k_proj(const float* __restrict__ x, const float* __restrict__ W, int n) {
    __shared__ float sW[2 * DD];
    int t = threadIdx.x;
    if (t < 2 * DD) sW[t] = W[t];
    __syncthreads();
    int gw = (blockIdx.x * blockDim.x + t) >> 5;
    int lane = t & 31;
    if (gw >= n) return;
    const float* xr = x + (size_t)gw * DD;
    float a  = xr[lane];
    float b2 = xr[lane + 32];
    float s0 = a * sW[lane]      + b2 * sW[lane + 32];
    float s1 = a * sW[DD + lane] + b2 * sW[DD + lane + 32];
    #pragma unroll
    for (int o = 16; o; o >>= 1) {
        s0 += __shfl_xor_sync(0xffffffffu, s0, o);
        s1 += __shfl_xor_sync(0xffffffffu, s1, o);
    }
    if (lane == 0) {
        float d = rsqrtf((float)g_deg[gw]);
        g_dinv[gw] = d;
        g_z0[gw] = make_float2(d * s0, d * s1);
        g_a1[gw].z = d * d;
    }
}

// hop 1: a1.xy[c] += z0[r]; edges [0,e) + self-loop tail [e, e+n)
__global__ void k_edge1(int e, int n) {
    int i = blockIdx.x * blockDim.x + threadIdx.x;
    if (i < e) {
        int2 rc = g_rc[i];
        float2 v = __ldg(&g_z0[rc.x]);
        red_add_f2((float2*)&g_a1[rc.y], v.x, v.y);
    } else if (i < e + n) {
        int j = i - e;
        float2 v = __ldg(&g_z0[j]);
        red_add_f2((float2*)&g_a1[j], v.x, v.y);
    }
}

// hop 2: t2[c] += d2[r]*t1[r], one 16B gather per edge
__global__ void k_edge2(int e, int n) {
    int i = blockIdx.x * blockDim.x + threadIdx.x;
    if (i < e) {
        int2 rc = g_rc[i];
        float4 a = __ldg(&g_a1[rc.x]);
        red_add_f2(&g_t2[rc.y], a.z * a.x, a.z * a.y);
    } else if (i < e + n) {
        int j = i - e;
        float4 a = __ldg(&g_a1[j]);
        red_add_f2(&g_t2[j], a.z * a.x, a.z * a.y);
    }
}

// out = log_softmax(dinv * t2 + b) over C=2
__global__ void k_out(const float* __restrict__ b, float* __restrict__ out, int n) {
    int i = blockIdx.x * blockDim.x + threadIdx.x;
    if (i >= n) return;
    float d = g_dinv[i];
    float2 y = g_t2[i];
    float l0 = d * y.x + b[0];
    float l1 = d * y.y + b[1];
    float m = fmaxf(l0, l1);
    float lse = m + logf(expf(l0 - m) + expf(l1 - m));
    *(float2*)(out + 2 * i) = make_float2(l0 - lse, l1 - lse);
}

// ---------------- launch ----------------

extern "C" void kernel_launch(void* const* d_in, const int* in_sizes, int n_in,
                              void* d_out, int out_size) {
    const float* x    = (const float*)d_in[0];
    const void*  edge = d_in[1];
    const float* W    = (const float*)d_in[2];
    const float* b    = (const float*)d_in[3];
    float*       out  = (float*)d_out;

    int n = in_sizes[0] / DD;   // 100000
    int e = in_sizes[1] / 2;    // 1600000

    const int T = 256;
    int gn  = (n + T - 1) / T;
    int gc  = ((e + 3) / 4 + T - 1) / T;
    int gen = (e + n + T - 1) / T;
    int gw  = ((size_t)n * 32 + T - 1) / T;

    k_init<<<gn, T>>>(edge, n);
    k_count<<<gc, T>>>(edge, e, n);
    k_proj<<<gw, T>>>(x, W, n);
    k_edge1<<<gen, T>>>(e, n);
    k_edge2<<<gen, T>>>(e, n);
    k_out<<<gn, T>>>(b, out, n);
}